// round 5
// baseline (speedup 1.0000x reference)
#include <cuda_runtime.h>

// out[n, d, t] = mean over d' of in[n, d', t]
// in: [32768, 64, 64] fp32. Compulsory traffic: 512MB read + 512MB write.
// Mixed R/W stream plateaus at ~80% of HBM spec (measured 4x). Split into
// unidirectional phases to avoid DRAM bus turnaround:
//   k1: read 512MB, write 8MB means to __device__ scratch  (read-dominated)
//   k2: read 8MB means (L2-resident), write 512MB          (write-dominated)

static constexpr int N_AGENTS = 32768;
static constexpr int FEAT_DIM = 64;
static constexpr int QUADS_PER_ROW = 16;   // 64 t / 4
static constexpr int F4_PER_AGENT = 1024;  // 64*64/4
static constexpr int TOTAL_ITEMS = N_AGENTS * QUADS_PER_ROW;  // 524288

// 8MB scratch: mean[agent][tq] as float4
__device__ float4 g_mean[TOTAL_ITEMS];

__global__ void __launch_bounds__(256)
mean_reduce_kernel(const float4* __restrict__ in) {
    int gid = blockIdx.x * blockDim.x + threadIdx.x;
    int agent = gid >> 4;
    int tq = gid & 15;

    const float4* __restrict__ row = in + (size_t)agent * F4_PER_AGENT + tq;

    float ax = 0.f, ay = 0.f, az = 0.f, aw = 0.f;
    #pragma unroll 16
    for (int d = 0; d < FEAT_DIM; d++) {
        float4 v = __ldcs(&row[d * QUADS_PER_ROW]);
        ax += v.x; ay += v.y; az += v.z; aw += v.w;
    }
    const float inv = 1.0f / (float)FEAT_DIM;
    float4 m;
    m.x = ax * inv; m.y = ay * inv; m.z = az * inv; m.w = aw * inv;
    g_mean[gid] = m;   // default policy: keep resident in L2 for phase 2
}

__global__ void __launch_bounds__(256)
mean_bcast_kernel(float4* __restrict__ out) {
    int gid = blockIdx.x * blockDim.x + threadIdx.x;
    int agent = gid >> 4;
    int tq = gid & 15;

    float4 m = g_mean[gid];   // L2 hit (written by phase 1 just before)

    float4* __restrict__ orow = out + (size_t)agent * F4_PER_AGENT + tq;
    #pragma unroll 16
    for (int d = 0; d < FEAT_DIM; d++) {
        __stcs(&orow[d * QUADS_PER_ROW], m);
    }
}

extern "C" void kernel_launch(void* const* d_in, const int* in_sizes, int n_in,
                              void* d_out, int out_size) {
    const float4* in = (const float4*)d_in[0];
    float4* out = (float4*)d_out;
    // seq_start_end (d_in[1]) is a no-op: contiguous partition, mean is per-agent.
    int block = 256;
    int grid = TOTAL_ITEMS / block;   // 2048
    mean_reduce_kernel<<<grid, block>>>(in);
    mean_bcast_kernel<<<grid, block>>>(out);
}